// round 8
// baseline (speedup 1.0000x reference)
#include <cuda_runtime.h>

#define HH 512
#define WW 512
#define NIMG 12
#define RAD 3
#define TX 64
#define TY 32
#define TILE_H 38            // TY + 2*RAD
#define SV_H   35            // TY + RAD
#define PITCH2 82            // pairs/row; row stride 656B = 16 mod 128 (stage-3 phase mapping)

typedef unsigned long long u64;

// interleaved {im, pt} ping-pong scratch (allocation-free static device globals)
__device__ u64 g_A[NIMG*HH*WW];
__device__ u64 g_B[NIMG*HH*WW];

__device__ __forceinline__ u64 ADD2(u64 a, u64 b) {
    u64 c; asm("add.rn.f32x2 %0, %1, %2;" : "=l"(c) : "l"(a), "l"(b)); return c;
}
__device__ __forceinline__ u64 SUB2(u64 a, u64 b) {
    u64 c; asm("sub.rn.f32x2 %0, %1, %2;" : "=l"(c) : "l"(a), "l"(b)); return c;
}
__device__ __forceinline__ u64 MUL2(u64 a, u64 b) {
    u64 c; asm("mul.rn.f32x2 %0, %1, %2;" : "=l"(c) : "l"(a), "l"(b)); return c;
}
__device__ __forceinline__ u64 PK(float lo, float hi) {
    u64 r; asm("mov.b64 %0, {%1, %2};" : "=l"(r) : "f"(lo), "f"(hi)); return r;
}
__device__ __forceinline__ float LOF(u64 v) {
    float lo, hi; asm("mov.b64 {%0, %1}, %2;" : "=f"(lo), "=f"(hi) : "l"(v)); return lo;
}
__device__ __forceinline__ float HIF(u64 v) {
    float lo, hi; asm("mov.b64 {%0, %1}, %2;" : "=f"(lo), "=f"(hi) : "l"(v)); return hi;
}

// opaque (non-CSE-able) scalar shared loads for lazy mid-value fetch
__device__ __forceinline__ u64 LDS64_AT(unsigned addr) {
    u64 v; asm("ld.shared.b64 %0, [%1];" : "=l"(v) : "r"(addr)); return v;
}
__device__ __forceinline__ float LDSF_AT(unsigned addr) {
    float v; asm("ld.shared.f32 %0, [%1];" : "=f"(v) : "r"(addr)); return v;
}
__device__ __forceinline__ unsigned SADDR(const void* p) {
    unsigned a;
    asm("{.reg .u64 t; cvta.to.shared.u64 t, %1; cvt.u32.u64 %0, t;}" : "=r"(a) : "l"(p));
    return a;
}

// Packed sliding 4-sum tree over 10 pairs; outputs only the 7 sums (mids fetched lazily).
__device__ __forceinline__ void tree7p(const u64* __restrict__ base, u64* __restrict__ q) {
    ulonglong2 A0 = ((const ulonglong2*)base)[0];
    ulonglong2 A1 = ((const ulonglong2*)base)[1];
    ulonglong2 A2 = ((const ulonglong2*)base)[2];
    ulonglong2 A3 = ((const ulonglong2*)base)[3];
    ulonglong2 A4 = ((const ulonglong2*)base)[4];
    u64 w0=ADD2(A0.x,A1.x), w1=ADD2(A0.y,A1.y), w2=ADD2(A1.x,A2.x), w3=ADD2(A1.y,A2.y),
        w4=ADD2(A2.x,A3.x), w5=ADD2(A2.y,A3.y), w6=ADD2(A3.x,A4.x), w7=ADD2(A3.y,A4.y);
    q[0]=ADD2(w0,w1); q[1]=ADD2(w1,w2); q[2]=ADD2(w2,w3); q[3]=ADD2(w3,w4);
    q[4]=ADD2(w4,w5); q[5]=ADD2(w5,w6); q[6]=ADD2(w6,w7);
}

// mode 0: read split float im/pt, write interleaved pairs
// mode 1: read pairs, write pairs
// mode 2: read pairs, write pert floats to d_out
__global__ __launch_bounds__(256, 4)
void swf_step(const float* __restrict__ im_in, const float* __restrict__ pt_in,
              const u64* __restrict__ z_in, u64* __restrict__ z_out,
              float* __restrict__ pt_out, int mode)
{
    __shared__ u64 s [TILE_H][PITCH2];   // {im, pt} pairs
    __shared__ u64 sv[SV_H][PITCH2];     // vertical 4-row sums, packed

    const int img = blockIdx.z;
    const int x0 = blockIdx.x * TX;
    const int y0 = blockIdx.y * TY;
    const int tid = threadIdx.x;

    // ---- stage 1: load tile with halo ----
    if (mode == 0) {
        const float* __restrict__ imI = im_in + (size_t)img * HH * WW;
        const float* __restrict__ ptI = pt_in + (size_t)img * HH * WW;
        for (int r = tid; r < TILE_H * 16; r += 256) {
            int ly = r >> 4, lx4 = (r & 15) << 2;
            int gy = y0 - RAD + ly;
            float4 a = make_float4(0.f,0.f,0.f,0.f), b = a;
            if (gy >= 0 && gy < HH) {
                a = *(const float4*)(imI + gy * WW + x0 + lx4);
                b = *(const float4*)(ptI + gy * WW + x0 + lx4);
            }
            s[ly][lx4 + 3] = PK(a.x, b.x);
            s[ly][lx4 + 4] = PK(a.y, b.y);
            s[ly][lx4 + 5] = PK(a.z, b.z);
            s[ly][lx4 + 6] = PK(a.w, b.w);
        }
        for (int r = tid; r < TILE_H * 6; r += 256) {
            int ly = r / 6, hx = r - ly * 6;
            int lx = (hx < 3) ? hx : hx + 64;        // cols 0,1,2 and 67,68,69
            int gy = y0 - RAD + ly, gx = x0 - RAD + lx;
            float a = 0.f, b = 0.f;
            if (gy >= 0 && gy < HH && gx >= 0 && gx < WW) {
                int g = gy * WW + gx;
                a = imI[g]; b = ptI[g];
            }
            s[ly][lx] = PK(a, b);
        }
    } else {
        const u64* __restrict__ zI = z_in + (size_t)img * HH * WW;
        for (int r = tid; r < TILE_H * 16; r += 256) {
            int ly = r >> 4, lx4 = (r & 15) << 2;
            int gy = y0 - RAD + ly;
            ulonglong2 a = make_ulonglong2(0ull, 0ull), b = a;
            if (gy >= 0 && gy < HH) {
                const ulonglong2* src = (const ulonglong2*)(zI + gy * WW + x0 + lx4);
                a = src[0]; b = src[1];
            }
            s[ly][lx4 + 3] = a.x;
            s[ly][lx4 + 4] = a.y;
            s[ly][lx4 + 5] = b.x;
            s[ly][lx4 + 6] = b.y;
        }
        for (int r = tid; r < TILE_H * 6; r += 256) {
            int ly = r / 6, hx = r - ly * 6;
            int lx = (hx < 3) ? hx : hx + 64;
            int gy = y0 - RAD + ly, gx = x0 - RAD + lx;
            u64 v = 0ull;
            if (gy >= 0 && gy < HH && gx >= 0 && gx < WW)
                v = zI[gy * WW + gx];
            s[ly][lx] = v;
        }
    }
    __syncthreads();

    // ---- stage 2: vertical 4-row sums, packed (one pass covers both arrays) ----
    for (int r = tid; r < SV_H * 32; r += 256) {
        int j = r >> 5, lx = (r & 31) << 1;          // pair cols 0..63
        ulonglong2 r0 = *(const ulonglong2*)&s[j    ][lx];
        ulonglong2 r1 = *(const ulonglong2*)&s[j + 1][lx];
        ulonglong2 r2 = *(const ulonglong2*)&s[j + 2][lx];
        ulonglong2 r3 = *(const ulonglong2*)&s[j + 3][lx];
        ulonglong2 o;
        o.x = ADD2(ADD2(r0.x, r1.x), ADD2(r2.x, r3.x));
        o.y = ADD2(ADD2(r0.y, r1.y), ADD2(r2.y, r3.y));
        *(ulonglong2*)&sv[j][lx] = o;
    }
    for (int r = tid; r < SV_H * 4; r += 256) {
        int j = r >> 2, lx = 64 + ((r & 3) << 1);    // pair cols 64..71
        ulonglong2 r0 = *(const ulonglong2*)&s[j    ][lx];
        ulonglong2 r1 = *(const ulonglong2*)&s[j + 1][lx];
        ulonglong2 r2 = *(const ulonglong2*)&s[j + 2][lx];
        ulonglong2 r3 = *(const ulonglong2*)&s[j + 3][lx];
        ulonglong2 o;
        o.x = ADD2(ADD2(r0.x, r1.x), ADD2(r2.x, r3.x));
        o.y = ADD2(ADD2(r0.y, r1.y), ADD2(r2.y, r3.y));
        *(ulonglong2*)&sv[j][lx] = o;
    }
    __syncthreads();

    // ---- stage 3: 8 px/thread, 2 chunks of 4 px; packed im+pt in one pass ----
    const int oy  = ((tid >> 5) << 2) | (tid & 3);   // 0..31
    const int j   = (tid >> 2) & 7;
    const int xch = ((j & 1) << 1) | ((j >> 1) & 1) | (j & 4);  // bijection 0..7
    const int xb  = xch << 2;                        // pair units 0,4,...,28

    const u64 c28 = PK(1.f/28.f, 1.f/28.f);
    const u64 c16 = PK(1.f/16.f, 1.f/16.f);

    const unsigned svA = SADDR(&sv[0][0]);
    const unsigned sA  = SADDR(&s[0][0]);

    const int growp = img * HH * WW + (y0 + oy) * WW + x0;

    #pragma unroll
    for (int ch = 0; ch < 2; ch++) {
        const int xs = xb + (ch << 5);
        u64 qu[7], qv[7], hq[7];
        tree7p(&sv[oy    ][xs], qu);
        tree7p(&sv[oy + 3][xs], qv);
        tree7p(&s [oy + 3][xs], hq);

        const unsigned aU = svA + (unsigned)((oy * PITCH2 + xs + 3) << 3);
        const unsigned aV = svA + (unsigned)(((oy + 3) * PITCH2 + xs + 3) << 3);
        const unsigned aC = sA  + (unsigned)(((oy + 3) * PITCH2 + xs + 3) << 3);

        u64 win[4];
        #pragma unroll
        for (int p = 0; p < 4; p++) {
            u64 qnw = qu[p], qne = qu[p+3], qsw = qv[p], qse = qv[p+3];
            u64 mu_p = LDS64_AT(aU + (p << 3));      // sv[oy][xs+3+p]
            u64 mv_p = LDS64_AT(aV + (p << 3));      // sv[oy+3][xs+3+p]
            float zl = LDSF_AT(aC + (p << 3));       // lo(im) of s[oy+3][xs+3+p]
            u64 d0 = MUL2(SUB2(ADD2(qnw, qsw), hq[p]  ), c28);  // L
            u64 d1 = MUL2(SUB2(ADD2(qne, qse), hq[p+3]), c28);  // R
            u64 d2 = MUL2(SUB2(ADD2(qnw, qne), mu_p   ), c28);  // U
            u64 d3 = MUL2(SUB2(ADD2(qsw, qse), mv_p   ), c28);  // D
            u64 d4 = MUL2(qnw, c16);                            // NW
            u64 d5 = MUL2(qne, c16);                            // NE
            u64 d6 = MUL2(qsw, c16);                            // SW
            u64 d7 = MUL2(qse, c16);                            // SE
            float a0 = fabsf(LOF(d0) - zl), a1 = fabsf(LOF(d1) - zl);
            float a2 = fabsf(LOF(d2) - zl), a3 = fabsf(LOF(d3) - zl);
            float a4 = fabsf(LOF(d4) - zl), a5 = fabsf(LOF(d5) - zl);
            float a6 = fabsf(LOF(d6) - zl), a7 = fabsf(LOF(d7) - zl);
            // tournament argmin on lo (im); winner pair carries both outputs.
            // strict <: left wins ties == first minimum (matches argmin).
            bool t;
            t = a1 < a0;  float a01 = t ? a1 : a0;  u64 v01 = t ? d1 : d0;
            t = a3 < a2;  float a23 = t ? a3 : a2;  u64 v23 = t ? d3 : d2;
            t = a5 < a4;  float a45 = t ? a5 : a4;  u64 v45 = t ? d5 : d4;
            t = a7 < a6;  float a67 = t ? a7 : a6;  u64 v67 = t ? d7 : d6;
            t = a23 < a01;  float a03 = t ? a23 : a01;  u64 v03 = t ? v23 : v01;
            t = a67 < a45;  float a47 = t ? a67 : a45;  u64 v47 = t ? v67 : v45;
            win[p] = (a47 < a03) ? v47 : v03;
        }

        if (mode != 2) {
            *(ulonglong2*)(z_out + growp + xs    ) = make_ulonglong2(win[0], win[1]);
            *(ulonglong2*)(z_out + growp + xs + 2) = make_ulonglong2(win[2], win[3]);
        } else {
            *(float4*)(pt_out + growp + xs) =
                make_float4(HIF(win[0]), HIF(win[1]), HIF(win[2]), HIF(win[3]));
        }
    }
}

extern "C" void kernel_launch(void* const* d_in, const int* in_sizes, int n_in,
                              void* d_out, int out_size)
{
    const float* im = (const float*)d_in[0];
    const float* pt = (const float*)d_in[1];
    float* out = (float*)d_out;

    u64 *A, *B;
    cudaGetSymbolAddress((void**)&A, g_A);
    cudaGetSymbolAddress((void**)&B, g_B);

    dim3 grid(WW / TX, HH / TY, NIMG);   // (8,16,12) = 1536 blocks
    dim3 block(256);

    swf_step<<<grid, block>>>(im, pt, nullptr, A, nullptr, 0);       // in -> A
    swf_step<<<grid, block>>>(nullptr, nullptr, A, B, nullptr, 1);   // A -> B
    swf_step<<<grid, block>>>(nullptr, nullptr, B, A, nullptr, 1);   // B -> A
    swf_step<<<grid, block>>>(nullptr, nullptr, A, B, nullptr, 1);   // A -> B
    swf_step<<<grid, block>>>(nullptr, nullptr, B, A, nullptr, 1);   // B -> A
    swf_step<<<grid, block>>>(nullptr, nullptr, A, nullptr, out, 2); // A -> out (pert)
}

// round 9
// speedup vs baseline: 1.1565x; 1.1565x over previous
#include <cuda_runtime.h>

#define HH 512
#define WW 512
#define NIMG 12
#define RAD 3
#define TX 64
#define TY 32
#define TILE_H 38            // TY + 2*RAD
#define SV_H   35            // TY + RAD
#define PITCH  76            // padded shared pitch (float4-aligned)
// halo storage offset = 4: output pixel x <-> smem col x+4; window cols x+1..x+7.
// main region gx in [x0, x0+64) -> smem cols 4..67 (16B-aligned STS.128);
// halo cols 1,2,3 (left) and 68,69,70 (right). Cols 0 and 71 are never-read garbage.

typedef unsigned long long u64;

// ping-pong scratch (allocation-free: static device globals)
__device__ float g_imA[NIMG*HH*WW];
__device__ float g_ptA[NIMG*HH*WW];
__device__ float g_imB[NIMG*HH*WW];
__device__ float g_ptB[NIMG*HH*WW];

__device__ __forceinline__ u64 ADD2(u64 a, u64 b) {
    u64 c; asm("add.rn.f32x2 %0, %1, %2;" : "=l"(c) : "l"(a), "l"(b)); return c;
}

__global__ __launch_bounds__(256, 4)
void swf_step(const float* __restrict__ im_in, const float* __restrict__ pt_in,
              float* __restrict__ im_out, float* __restrict__ pt_out,
              int write_im)
{
    __shared__ float s [2][TILE_H][PITCH];
    __shared__ float sv[2][SV_H][PITCH];

    const int img = blockIdx.z;
    const int x0 = blockIdx.x * TX;
    const int y0 = blockIdx.y * TY;
    const float* __restrict__ imI = im_in + (size_t)img * HH * WW;
    const float* __restrict__ ptI = pt_in + (size_t)img * HH * WW;

    const int tid = threadIdx.x;

    // ---- stage 1a: main region via LDG.128 -> aligned STS.128 (y-check only) ----
    {
        const int PER_A = TILE_H * 16;             // 608 f4-groups per array
        for (int r = tid; r < 2 * PER_A; r += 256) {
            int a  = r >= PER_A;
            int rr = r - (a ? PER_A : 0);
            int ly = rr >> 4, lx4 = (rr & 15) << 2;
            int gy = y0 - RAD + ly;
            const float* src = a ? ptI : imI;
            float4 val = make_float4(0.f, 0.f, 0.f, 0.f);
            if (gy >= 0 && gy < HH)
                val = *(const float4*)(src + gy * WW + x0 + lx4);
            *(float4*)&s[a][ly][lx4 + 4] = val;    // 16B-aligned
        }
    }
    // ---- stage 1b: 6 halo columns (cols 1,2,3 and 68,69,70), scalar, full bounds ----
    {
        const int PER_A = TILE_H * 6;
        for (int r = tid; r < 2 * PER_A; r += 256) {
            int a  = r >= PER_A;
            int rr = r - (a ? PER_A : 0);
            int ly = rr / 6;
            int hx = rr - 6 * ly;
            int lx = (hx < 3) ? hx + 1 : hx + 65;  // 1,2,3 / 68,69,70
            int gy = y0 - RAD + ly, gx = x0 - 4 + lx;
            float val = 0.f;
            if (gy >= 0 && gy < HH && gx >= 0 && gx < WW)
                val = (a ? ptI : imI)[gy * WW + gx];
            s[a][ly][lx] = val;
        }
    }
    __syncthreads();

    // ---- stage 2: vertical 4-row sums with packed f32x2 (lane-independent, safe) ----
    #pragma unroll
    for (int a = 0; a < 2; a++) {
        for (int r = tid; r < SV_H * 16; r += 256) {
            int j = r >> 4, lx = (r & 15) << 2;
            ulonglong2 r0 = *(const ulonglong2*)&s[a][j    ][lx];
            ulonglong2 r1 = *(const ulonglong2*)&s[a][j + 1][lx];
            ulonglong2 r2 = *(const ulonglong2*)&s[a][j + 2][lx];
            ulonglong2 r3 = *(const ulonglong2*)&s[a][j + 3][lx];
            ulonglong2 o;
            o.x = ADD2(ADD2(r0.x, r1.x), ADD2(r2.x, r3.x));
            o.y = ADD2(ADD2(r0.y, r1.y), ADD2(r2.y, r3.y));
            *(ulonglong2*)&sv[a][j][lx] = o;
        }
        for (int r = tid; r < SV_H * 2; r += 256) {
            int j = r >> 1, lx = 64 + ((r & 1) << 2);
            ulonglong2 r0 = *(const ulonglong2*)&s[a][j    ][lx];
            ulonglong2 r1 = *(const ulonglong2*)&s[a][j + 1][lx];
            ulonglong2 r2 = *(const ulonglong2*)&s[a][j + 2][lx];
            ulonglong2 r3 = *(const ulonglong2*)&s[a][j + 3][lx];
            ulonglong2 o;
            o.x = ADD2(ADD2(r0.x, r1.x), ADD2(r2.x, r3.x));
            o.y = ADD2(ADD2(r0.y, r1.y), ADD2(r2.y, r3.y));
            *(ulonglong2*)&sv[a][j][lx] = o;
        }
    }
    __syncthreads();

    // ---- stage 3: 8 px per thread, 2 independent 4-px chunks 32 cols apart ----
    // Loads are aligned f4 at xs, xs+4, xs+8; window uses elements 1..10 of the 12.
    const int oy  = tid >> 3;                 // 0..31
    const int xb  = (tid & 7) << 2;           // 0,4,...,28
    const float inv16 = 1.f / 16.f;
    const float inv28 = 1.f / 28.f;

    float u[12], v[12], c[12];
    float qu[7], qv[7], hc[7];

    #define LOAD3(A, XS)                                                     \
        {                                                                    \
            float4 t0, t1, t2;                                               \
            t0 = *(const float4*)&sv[A][oy][(XS)];                           \
            t1 = *(const float4*)&sv[A][oy][(XS) + 4];                       \
            t2 = *(const float4*)&sv[A][oy][(XS) + 8];                       \
            u[0]=t0.x; u[1]=t0.y; u[2]=t0.z; u[3]=t0.w;                      \
            u[4]=t1.x; u[5]=t1.y; u[6]=t1.z; u[7]=t1.w;                      \
            u[8]=t2.x; u[9]=t2.y; u[10]=t2.z; u[11]=t2.w;                    \
            t0 = *(const float4*)&sv[A][oy + 3][(XS)];                       \
            t1 = *(const float4*)&sv[A][oy + 3][(XS) + 4];                   \
            t2 = *(const float4*)&sv[A][oy + 3][(XS) + 8];                   \
            v[0]=t0.x; v[1]=t0.y; v[2]=t0.z; v[3]=t0.w;                      \
            v[4]=t1.x; v[5]=t1.y; v[6]=t1.z; v[7]=t1.w;                      \
            v[8]=t2.x; v[9]=t2.y; v[10]=t2.z; v[11]=t2.w;                    \
            t0 = *(const float4*)&s[A][oy + 3][(XS)];                        \
            t1 = *(const float4*)&s[A][oy + 3][(XS) + 4];                    \
            t2 = *(const float4*)&s[A][oy + 3][(XS) + 8];                    \
            c[0]=t0.x; c[1]=t0.y; c[2]=t0.z; c[3]=t0.w;                      \
            c[4]=t1.x; c[5]=t1.y; c[6]=t1.z; c[7]=t1.w;                      \
            c[8]=t2.x; c[9]=t2.y; c[10]=t2.z; c[11]=t2.w;                    \
        }

    // sums over window indices 1..10 (element 0 and 11 are outside the window)
    #define QSUMS()                                                         \
        {                                                                    \
            float pu[9], pv[9], pc[9];                                       \
            _Pragma("unroll")                                                \
            for (int i = 0; i < 9; i++) {                                    \
                pu[i] = u[i+1] + u[i+2];                                     \
                pv[i] = v[i+1] + v[i+2];                                     \
                pc[i] = c[i+1] + c[i+2];                                     \
            }                                                                \
            _Pragma("unroll")                                                \
            for (int i = 0; i < 7; i++) {                                    \
                qu[i] = pu[i] + pu[i+2];                                     \
                qv[i] = pv[i] + pv[i+2];                                     \
                hc[i] = pc[i] + pc[i+2];                                     \
            }                                                                \
        }

    const int grow = img * HH * WW + (y0 + oy) * WW + x0;
    unsigned pack[2];

    // ===== pass A: im -> packed argmin indices + filtered im =====
    #pragma unroll
    for (int ch = 0; ch < 2; ch++) {
        const int xs = xb + (ch << 5);
        LOAD3(0, xs)
        QSUMS()
        float bi[4];
        unsigned pk = 0;
        #pragma unroll
        for (int p = 0; p < 4; p++) {
            float qnw = qu[p], qne = qu[p+3], qsw = qv[p], qse = qv[p+3];
            float z = c[p+4];
            float dd[8];
            dd[0] = ((qnw + qsw) - hc[p  ]) * inv28;   // L
            dd[1] = ((qne + qse) - hc[p+3]) * inv28;   // R
            dd[2] = ((qnw + qne) - u[p+4]) * inv28;    // U
            dd[3] = ((qsw + qse) - v[p+4]) * inv28;    // D
            dd[4] = qnw * inv16;                       // NW
            dd[5] = qne * inv16;                       // NE
            dd[6] = qsw * inv16;                       // SW
            dd[7] = qse * inv16;                       // SE
            // tournament argmin, left wins ties == first minimum
            float aa[8];
            #pragma unroll
            for (int k = 0; k < 8; k++) aa[k] = fabsf(dd[k] - z);
            float a01 = aa[1] < aa[0] ? aa[1] : aa[0];  float v01 = aa[1] < aa[0] ? dd[1] : dd[0];  int i01 = aa[1] < aa[0] ? 1 : 0;
            float a23 = aa[3] < aa[2] ? aa[3] : aa[2];  float v23 = aa[3] < aa[2] ? dd[3] : dd[2];  int i23 = aa[3] < aa[2] ? 3 : 2;
            float a45 = aa[5] < aa[4] ? aa[5] : aa[4];  float v45 = aa[5] < aa[4] ? dd[5] : dd[4];  int i45 = aa[5] < aa[4] ? 5 : 4;
            float a67 = aa[7] < aa[6] ? aa[7] : aa[6];  float v67 = aa[7] < aa[6] ? dd[7] : dd[6];  int i67 = aa[7] < aa[6] ? 7 : 6;
            float a03 = a23 < a01 ? a23 : a01;  float v03 = a23 < a01 ? v23 : v01;  int i03 = a23 < a01 ? i23 : i01;
            float a47 = a67 < a45 ? a67 : a45;  float v47 = a67 < a45 ? v67 : v45;  int i47 = a67 < a45 ? i67 : i45;
            float bv = a47 < a03 ? v47 : v03;
            int   bk = a47 < a03 ? i47 : i03;
            bi[p] = bv;
            pk |= (unsigned)bk << (3 * p);
        }
        pack[ch] = pk;
        if (write_im)
            *(float4*)&im_out[grow + xs] = make_float4(bi[0], bi[1], bi[2], bi[3]);
    }

    // ===== pass B: pert, select by stored index =====
    #pragma unroll
    for (int ch = 0; ch < 2; ch++) {
        const int xs = xb + (ch << 5);
        LOAD3(1, xs)
        QSUMS()
        float bp[4];
        unsigned pk = pack[ch];
        #pragma unroll
        for (int p = 0; p < 4; p++) {
            float qnw = qu[p], qne = qu[p+3], qsw = qv[p], qse = qv[p+3];
            float d0 = ((qnw + qsw) - hc[p  ]) * inv28;
            float d1 = ((qne + qse) - hc[p+3]) * inv28;
            float d2 = ((qnw + qne) - u[p+4]) * inv28;
            float d3 = ((qsw + qse) - v[p+4]) * inv28;
            float d4 = qnw * inv16;
            float d5 = qne * inv16;
            float d6 = qsw * inv16;
            float d7 = qse * inv16;
            int bk = (pk >> (3 * p)) & 7;
            float e0 = (bk & 1) ? d1 : d0;
            float e1 = (bk & 1) ? d3 : d2;
            float e2 = (bk & 1) ? d5 : d4;
            float e3 = (bk & 1) ? d7 : d6;
            float f0 = (bk & 2) ? e1 : e0;
            float f1 = (bk & 2) ? e3 : e2;
            bp[p] = (bk & 4) ? f1 : f0;
        }
        *(float4*)&pt_out[grow + xs] = make_float4(bp[0], bp[1], bp[2], bp[3]);
    }
}

extern "C" void kernel_launch(void* const* d_in, const int* in_sizes, int n_in,
                              void* d_out, int out_size)
{
    const float* im = (const float*)d_in[0];
    const float* pt = (const float*)d_in[1];
    float* out = (float*)d_out;

    float *imA, *ptA, *imB, *ptB;
    cudaGetSymbolAddress((void**)&imA, g_imA);
    cudaGetSymbolAddress((void**)&ptA, g_ptA);
    cudaGetSymbolAddress((void**)&imB, g_imB);
    cudaGetSymbolAddress((void**)&ptB, g_ptB);

    dim3 grid(WW / TX, HH / TY, NIMG);   // (8,16,12) = 1536 blocks
    dim3 block(256);

    swf_step<<<grid, block>>>(im,  pt,  imA, ptA, 1);
    swf_step<<<grid, block>>>(imA, ptA, imB, ptB, 1);
    swf_step<<<grid, block>>>(imB, ptB, imA, ptA, 1);
    swf_step<<<grid, block>>>(imA, ptA, imB, ptB, 1);
    swf_step<<<grid, block>>>(imB, ptB, imA, ptA, 1);
    swf_step<<<grid, block>>>(imA, ptA, imB, out, 0);
}